// round 1
// baseline (speedup 1.0000x reference)
#include <cuda_runtime.h>
#include <math_constants.h>

// ---------------------------------------------------------------------------
// DetectionLoss: for each (level, batch, gt): argmin over anchors of
// (gx-px)^2+(gy-py)^2; valid = sqrt(min) < 2.5; CE(log_softmax at matched cls
// row, label) and L1(matched reg row vs gt box), weighted-summed; outputs
// (cls_sum/denom, reg_sum/denom, num_pos), denom = max(num_pos, 1).
// ---------------------------------------------------------------------------

#define NLVL 3
#define NB   16
#define NGT  128
#define NC   80
#define HW0  25600
#define HW1  6400
#define HW2  1600
#define CHUNK 400                 // anchors per block
#define CH0  (HW0 / CHUNK)        // 64
#define CH1  (HW1 / CHUNK)        // 16
#define CH2  (HW2 / CHUNK)        // 4
#define CHT  (CH0 + CH1 + CH2)    // 84 chunk-slots per batch
#define NTASK (NLVL * NB * NGT)   // 6144

__device__ unsigned long long g_best[NTASK];
__device__ float g_acc[3];        // cls_sum, reg_sum, num_pos

// ---- packed f32x2 helpers (sm_10x) ----
__device__ __forceinline__ unsigned long long pack2(float lo, float hi) {
    unsigned long long r;
    asm("mov.b64 %0, {%1, %2};" : "=l"(r) : "f"(lo), "f"(hi));
    return r;
}
__device__ __forceinline__ void unpack2(unsigned long long v, float& lo, float& hi) {
    asm("mov.b64 {%0, %1}, %2;" : "=f"(lo), "=f"(hi) : "l"(v));
}
__device__ __forceinline__ unsigned long long add2(unsigned long long a, unsigned long long b) {
    unsigned long long r;
    asm("add.rn.f32x2 %0, %1, %2;" : "=l"(r) : "l"(a), "l"(b));
    return r;
}
__device__ __forceinline__ unsigned long long mul2(unsigned long long a, unsigned long long b) {
    unsigned long long r;
    asm("mul.rn.f32x2 %0, %1, %2;" : "=l"(r) : "l"(a), "l"(b));
    return r;
}
__device__ __forceinline__ unsigned long long fma2(unsigned long long a, unsigned long long b,
                                                   unsigned long long c) {
    unsigned long long r;
    asm("fma.rn.f32x2 %0, %1, %2, %3;" : "=l"(r) : "l"(a), "l"(b), "l"(c));
    return r;
}

// ---------------------------------------------------------------------------
__global__ void k_init() {
    int t = blockIdx.x * blockDim.x + threadIdx.x;
    if (t < NTASK) g_best[t] = 0xFFFFFFFFFFFFFFFFull;
    if (t < 3) g_acc[t] = 0.0f;
}

// ---------------------------------------------------------------------------
// One block = (batch b, level, chunk of CHUNK anchors). 256 threads:
// gt = tid & 127, sub = tid >> 7 (each gt served by 2 threads, each scanning
// half the chunk in increasing index order -> strict '<' keeps first index).
// Merge across threads/blocks via atomicMin on (d2_bits << 32 | idx).
__global__ void __launch_bounds__(256, 4) k_argmin(
    const float* __restrict__ reg0, const float* __restrict__ reg1,
    const float* __restrict__ reg2, const float* __restrict__ gtb) {
    const int bx = blockIdx.x;
    const int b  = bx / CHT;
    const int r  = bx % CHT;
    int lvl, chunk, HW;
    const float* reg;
    if (r < CH0)            { lvl = 0; chunk = r;        reg = reg0; HW = HW0; }
    else if (r < CH0 + CH1) { lvl = 1; chunk = r - CH0;  reg = reg1; HW = HW1; }
    else                    { lvl = 2; chunk = r - CH0 - CH1; reg = reg2; HW = HW2; }
    const int cs = chunk * CHUNK;

    __shared__ __align__(16) float s_ax[CHUNK];
    __shared__ __align__(16) float s_ay[CHUNK];

    // stage anchor xy (SoA) — reg rows are float4 (x,y,w,h)
    const float4* rp = (const float4*)(reg + ((size_t)b * HW + cs) * 4);
    for (int a = threadIdx.x; a < CHUNK; a += 256) {
        float4 v = rp[a];
        s_ax[a] = v.x;
        s_ay[a] = v.y;
    }
    __syncthreads();

    const int gt  = threadIdx.x & 127;
    const int sub = threadIdx.x >> 7;

    const float2 g = *(const float2*)(gtb + ((size_t)(b * NGT + gt)) * 4);
    const unsigned long long ngx = pack2(-g.x, -g.x);
    const unsigned long long ngy = pack2(-g.y, -g.y);

    float best = CUDART_INF_F;
    int   bi   = 0;

    const int i0 = sub * (CHUNK / 2);
#pragma unroll 5
    for (int i = i0; i < i0 + (CHUNK / 2); i += 2) {
        unsigned long long axp = *(const unsigned long long*)(s_ax + i);
        unsigned long long ayp = *(const unsigned long long*)(s_ay + i);
        unsigned long long dx  = add2(axp, ngx);
        unsigned long long dy  = add2(ayp, ngy);
        unsigned long long d2p = fma2(dy, dy, mul2(dx, dx));
        float d0, d1;
        unpack2(d2p, d0, d1);
        if (d0 < best) { best = d0; bi = i; }
        if (d1 < best) { best = d1; bi = i + 1; }
    }

    unsigned long long key =
        ((unsigned long long)__float_as_uint(best) << 32) | (unsigned)(cs + bi);

    // intra-block pair reduce (halves global atomics)
    __shared__ unsigned long long skey[256];
    skey[threadIdx.x] = key;
    __syncthreads();
    if (sub == 0) {
        unsigned long long k2 = skey[threadIdx.x + 128];
        if (k2 < key) key = k2;
        atomicMin(&g_best[(lvl * NB + b) * NGT + gt], key);
    }
}

// ---------------------------------------------------------------------------
// One warp per (lvl, b, n) task: CE via warp logsumexp over 80 logits + L1.
__global__ void __launch_bounds__(128) k_loss(
    const float* __restrict__ c0, const float* __restrict__ c1,
    const float* __restrict__ c2, const float* __restrict__ r0,
    const float* __restrict__ r1, const float* __restrict__ r2,
    const float* __restrict__ gtb, const int* __restrict__ lbl) {
    const int w    = (blockIdx.x * blockDim.x + threadIdx.x) >> 5;  // 0..6143
    const int lane = threadIdx.x & 31;
    const int lvl  = w >> 11;
    const int rr   = w & 2047;
    const int b    = rr >> 7;
    const int n    = rr & 127;

    const unsigned long long key = g_best[w];
    const float d2  = __uint_as_float((unsigned)(key >> 32));
    const int   idx = (int)(unsigned)(key & 0xFFFFFFFFu);
    const float wt  = (__fsqrt_rn(d2) < 2.5f) ? 1.0f : 0.0f;

    const float* cls = (lvl == 0) ? c0 : ((lvl == 1) ? c1 : c2);
    const float* reg = (lvl == 0) ? r0 : ((lvl == 1) ? r1 : r2);
    const int    HW  = (lvl == 0) ? HW0 : ((lvl == 1) ? HW1 : HW2);

    const float* row = cls + ((size_t)b * HW + idx) * NC;
    float x0 = row[lane];
    float x1 = row[lane + 32];
    float x2 = (lane < 16) ? row[lane + 64] : -CUDART_INF_F;

    float m = fmaxf(fmaxf(x0, x1), x2);
#pragma unroll
    for (int o = 16; o; o >>= 1) m = fmaxf(m, __shfl_xor_sync(0xFFFFFFFFu, m, o));

    float s = __expf(x0 - m) * 0.0f;  // placeholder to keep types; replaced below
    s = expf(x0 - m) + expf(x1 - m) + ((lane < 16) ? expf(x2 - m) : 0.0f);

    const int label = lbl[rr + ((b * NGT + n) - rr)];  // == lbl[b*NGT + n] == lbl[rr]
    float xl = 0.0f;
    if (lane == label)           xl = x0;
    else if (lane + 32 == label) xl = x1;
    else if (lane + 64 == label) xl = x2;

#pragma unroll
    for (int o = 16; o; o >>= 1) {
        s  += __shfl_xor_sync(0xFFFFFFFFu, s, o);
        xl += __shfl_xor_sync(0xFFFFFFFFu, xl, o);
    }

    if (lane == 0) {
        const float ce = (m + logf(s)) - xl;
        const float4 p = *(const float4*)(reg + ((size_t)b * HW + idx) * 4);
        const float4 gg = *(const float4*)(gtb + ((size_t)(b * NGT + n)) * 4);
        const float l1 = fabsf(p.x - gg.x) + fabsf(p.y - gg.y) +
                         fabsf(p.z - gg.z) + fabsf(p.w - gg.w);
        atomicAdd(&g_acc[0], ce * wt);
        atomicAdd(&g_acc[1], l1 * wt);
        atomicAdd(&g_acc[2], wt);
    }
}

// ---------------------------------------------------------------------------
__global__ void k_fin(float* out) {
    const float np    = g_acc[2];
    const float denom = fmaxf(np, 1.0f);
    out[0] = g_acc[0] / denom;
    out[1] = g_acc[1] / denom;
    out[2] = np;
}

// ---------------------------------------------------------------------------
extern "C" void kernel_launch(void* const* d_in, const int* in_sizes, int n_in,
                              void* d_out, int out_size) {
    const float* c[3] = {0, 0, 0};
    const float* r[3] = {0, 0, 0};
    const float* gtb  = 0;
    const int*   lbl  = 0;
    for (int i = 0; i < n_in; i++) {
        switch (in_sizes[i]) {
            case NB * HW0 * NC: c[0] = (const float*)d_in[i]; break;  // 32768000
            case NB * HW1 * NC: c[1] = (const float*)d_in[i]; break;  // 8192000
            case NB * HW2 * NC: c[2] = (const float*)d_in[i]; break;  // 2048000
            case NB * HW0 * 4:  r[0] = (const float*)d_in[i]; break;  // 1638400
            case NB * HW1 * 4:  r[1] = (const float*)d_in[i]; break;  // 409600
            case NB * HW2 * 4:  r[2] = (const float*)d_in[i]; break;  // 102400
            case NB * NGT * 4:  gtb  = (const float*)d_in[i]; break;  // 8192
            case NB * NGT:      lbl  = (const int*)d_in[i];   break;  // 2048
        }
    }

    k_init<<<(NTASK + 255) / 256, 256>>>();
    k_argmin<<<NB * CHT, 256>>>(r[0], r[1], r[2], gtb);
    k_loss<<<NTASK / 4, 128>>>(c[0], c[1], c[2], r[0], r[1], r[2], gtb, lbl);
    k_fin<<<1, 1>>>((float*)d_out);
}

// round 2
// speedup vs baseline: 1.0854x; 1.0854x over previous
#include <cuda_runtime.h>
#include <math_constants.h>

// ---------------------------------------------------------------------------
// DetectionLoss, 3 kernels:
//  k_chunkmin: per (level,b,gt,chunk-of-400-anchors) min d2 (no index), plain
//              stores -> g_chunkmin. Packed f32x2 math, FMNMX accumulators.
//  k_loss:     per task (warp): global min over chunk mins, first-chunk via
//              ballot, exact index recovery by rescanning that one chunk
//              (bit-identical arithmetic), then CE (warp logsumexp) + L1,
//              atomicAdd into g_acc.
//  k_fin:      write 3 outputs, reset g_acc (replay-deterministic).
// ---------------------------------------------------------------------------

#define NLVL 3
#define NB   16
#define NGT  128
#define NC   80
#define HW0  25600
#define HW1  6400
#define HW2  1600
#define CHUNK 400
#define CH0  64
#define CH1  16
#define CH2  4
#define CHT  84                   // per-batch chunk slots
#define MAXCH 64
#define NTASK (NLVL * NB * NGT)   // 6144

// [(lvl*NB+b)*MAXCH + chunk]*NGT + gt  (only chunk < nch(lvl) slots used)
__device__ float g_chunkmin[NLVL * NB * MAXCH * NGT];
__device__ float g_acc[3];        // cls_sum, reg_sum, num_pos (zero-init ok)

// ---- packed f32x2 helpers (sm_10x) ----
__device__ __forceinline__ unsigned long long pack2(float lo, float hi) {
    unsigned long long r;
    asm("mov.b64 %0, {%1, %2};" : "=l"(r) : "f"(lo), "f"(hi));
    return r;
}
__device__ __forceinline__ void unpack2(unsigned long long v, float& lo, float& hi) {
    asm("mov.b64 {%0, %1}, %2;" : "=f"(lo), "=f"(hi) : "l"(v));
}
__device__ __forceinline__ unsigned long long add2(unsigned long long a, unsigned long long b) {
    unsigned long long r;
    asm("add.rn.f32x2 %0, %1, %2;" : "=l"(r) : "l"(a), "l"(b));
    return r;
}
__device__ __forceinline__ unsigned long long mul2(unsigned long long a, unsigned long long b) {
    unsigned long long r;
    asm("mul.rn.f32x2 %0, %1, %2;" : "=l"(r) : "l"(a), "l"(b));
    return r;
}
__device__ __forceinline__ unsigned long long fma2(unsigned long long a, unsigned long long b,
                                                   unsigned long long c) {
    unsigned long long r;
    asm("fma.rn.f32x2 %0, %1, %2, %3;" : "=l"(r) : "l"(a), "l"(b), "l"(c));
    return r;
}

// ---------------------------------------------------------------------------
// 1344 blocks x 128 threads: block = (b, level, chunk); thread = gt.
// Each thread scans all 400 anchors of the chunk, min-only, 4 anchors/iter.
__global__ void __launch_bounds__(128, 12) k_chunkmin(
    const float* __restrict__ reg0, const float* __restrict__ reg1,
    const float* __restrict__ reg2, const float* __restrict__ gtb) {
    const int bx = blockIdx.x;
    const int b  = bx / CHT;
    const int r  = bx % CHT;
    int lvl, chunk, HW;
    const float* reg;
    if (r < CH0)            { lvl = 0; chunk = r;             reg = reg0; HW = HW0; }
    else if (r < CH0 + CH1) { lvl = 1; chunk = r - CH0;       reg = reg1; HW = HW1; }
    else                    { lvl = 2; chunk = r - CH0 - CH1; reg = reg2; HW = HW2; }
    const int cs = chunk * CHUNK;

    __shared__ __align__(16) float s_ax[CHUNK];
    __shared__ __align__(16) float s_ay[CHUNK];

    const float4* rp = (const float4*)(reg + ((size_t)b * HW + cs) * 4);
    for (int a = threadIdx.x; a < CHUNK; a += 128) {
        float4 v = rp[a];
        s_ax[a] = v.x;
        s_ay[a] = v.y;
    }
    __syncthreads();

    const int gt = threadIdx.x;
    const float2 g = *(const float2*)(gtb + ((size_t)(b * NGT + gt)) * 4);
    const unsigned long long ngx = pack2(-g.x, -g.x);
    const unsigned long long ngy = pack2(-g.y, -g.y);

    float a0 = CUDART_INF_F, a1 = CUDART_INF_F, a2 = CUDART_INF_F, a3 = CUDART_INF_F;

#pragma unroll 5
    for (int i = 0; i < CHUNK; i += 4) {
        const float4 ax = *(const float4*)(s_ax + i);
        const float4 ay = *(const float4*)(s_ay + i);
        const unsigned long long dx0 = add2(pack2(ax.x, ax.y), ngx);
        const unsigned long long dx1 = add2(pack2(ax.z, ax.w), ngx);
        const unsigned long long dy0 = add2(pack2(ay.x, ay.y), ngy);
        const unsigned long long dy1 = add2(pack2(ay.z, ay.w), ngy);
        const unsigned long long d2p0 = fma2(dy0, dy0, mul2(dx0, dx0));
        const unsigned long long d2p1 = fma2(dy1, dy1, mul2(dx1, dx1));
        float d0, d1, d2, d3;
        unpack2(d2p0, d0, d1);
        unpack2(d2p1, d2, d3);
        a0 = fminf(a0, d0);
        a1 = fminf(a1, d1);
        a2 = fminf(a2, d2);
        a3 = fminf(a3, d3);
    }

    const float m = fminf(fminf(a0, a1), fminf(a2, a3));
    g_chunkmin[((size_t)(lvl * NB + b) * MAXCH + chunk) * NGT + gt] = m;
}

// ---------------------------------------------------------------------------
// One warp per (lvl, b, n) task. 1536 blocks x 128.
__global__ void __launch_bounds__(128) k_loss(
    const float* __restrict__ c0, const float* __restrict__ c1,
    const float* __restrict__ c2, const float* __restrict__ r0,
    const float* __restrict__ r1, const float* __restrict__ r2,
    const float* __restrict__ gtb, const int* __restrict__ lbl) {
    const int w    = (blockIdx.x * blockDim.x + threadIdx.x) >> 5;  // 0..6143
    const int lane = threadIdx.x & 31;
    const int lvl  = w >> 11;
    const int rr   = w & 2047;
    const int b    = rr >> 7;
    const int n    = rr & 127;

    const int nch   = MAXCH >> (2 * lvl);     // 64, 16, 4
    const size_t cb = (size_t)(lvl * NB + b) * MAXCH;

    // global min over chunk mins
    const float cm0 = (lane < nch)      ? g_chunkmin[(cb + lane) * NGT + n]      : CUDART_INF_F;
    const float cm1 = (lane + 32 < nch) ? g_chunkmin[(cb + lane + 32) * NGT + n] : CUDART_INF_F;
    float m = fminf(cm0, cm1);
#pragma unroll
    for (int o = 16; o; o >>= 1) m = fminf(m, __shfl_xor_sync(0xFFFFFFFFu, m, o));

    const float wt = (__fsqrt_rn(m) < 2.5f) ? 1.0f : 0.0f;

    // first chunk achieving the min
    const unsigned e0 = __ballot_sync(0xFFFFFFFFu, cm0 == m);
    const unsigned e1 = __ballot_sync(0xFFFFFFFFu, cm1 == m);
    const int chunk = e0 ? (__ffs(e0) - 1) : (32 + __ffs(e1) - 1);
    const int cs    = chunk * CHUNK;

    const float* cls = (lvl == 0) ? c0 : ((lvl == 1) ? c1 : c2);
    const float* reg = (lvl == 0) ? r0 : ((lvl == 1) ? r1 : r2);
    const int    HW  = (lvl == 0) ? HW0 : ((lvl == 1) ? HW1 : HW2);

    // exact index recovery: rescan the one winning chunk with identical math
    const float2 g = *(const float2*)(gtb + ((size_t)(b * NGT + n)) * 4);
    int minIdx = 0x7FFFFFFF;
    for (int a = lane; a < CHUNK; a += 32) {
        const float2 p = *(const float2*)(reg + ((size_t)b * HW + cs + a) * 4);
        const float dx = p.x - g.x;
        const float dy = p.y - g.y;
        const float d2 = __fmaf_rn(dy, dy, __fmul_rn(dx, dx));
        if (d2 == m) minIdx = min(minIdx, cs + a);
    }
#pragma unroll
    for (int o = 16; o; o >>= 1) minIdx = min(minIdx, __shfl_xor_sync(0xFFFFFFFFu, minIdx, o));
    const int idx = minIdx;

    // CE: warp logsumexp over 80 logits
    const float* row = cls + ((size_t)b * HW + idx) * NC;
    const float x0 = row[lane];
    const float x1 = row[lane + 32];
    const float x2 = (lane < 16) ? row[lane + 64] : -CUDART_INF_F;

    float mx = fmaxf(fmaxf(x0, x1), x2);
#pragma unroll
    for (int o = 16; o; o >>= 1) mx = fmaxf(mx, __shfl_xor_sync(0xFFFFFFFFu, mx, o));

    float s = expf(x0 - mx) + expf(x1 - mx) + ((lane < 16) ? expf(x2 - mx) : 0.0f);

    const int label = lbl[b * NGT + n];
    float xl = 0.0f;
    if (lane == label)           xl = x0;
    else if (lane + 32 == label) xl = x1;
    else if (lane + 64 == label) xl = x2;

#pragma unroll
    for (int o = 16; o; o >>= 1) {
        s  += __shfl_xor_sync(0xFFFFFFFFu, s, o);
        xl += __shfl_xor_sync(0xFFFFFFFFu, xl, o);
    }

    if (lane == 0) {
        const float ce = (mx + logf(s)) - xl;
        const float4 p  = *(const float4*)(reg + ((size_t)b * HW + idx) * 4);
        const float4 gg = *(const float4*)(gtb + ((size_t)(b * NGT + n)) * 4);
        const float l1 = fabsf(p.x - gg.x) + fabsf(p.y - gg.y) +
                         fabsf(p.z - gg.z) + fabsf(p.w - gg.w);
        atomicAdd(&g_acc[0], ce * wt);
        atomicAdd(&g_acc[1], l1 * wt);
        atomicAdd(&g_acc[2], wt);
    }
}

// ---------------------------------------------------------------------------
__global__ void k_fin(float* out) {
    if (threadIdx.x == 0) {
        const float np    = g_acc[2];
        const float denom = fmaxf(np, 1.0f);
        out[0] = g_acc[0] / denom;
        out[1] = g_acc[1] / denom;
        out[2] = np;
        g_acc[0] = 0.0f;   // reset after read: next replay starts clean
        g_acc[1] = 0.0f;
        g_acc[2] = 0.0f;
    }
}

// ---------------------------------------------------------------------------
extern "C" void kernel_launch(void* const* d_in, const int* in_sizes, int n_in,
                              void* d_out, int out_size) {
    const float* c[3] = {0, 0, 0};
    const float* r[3] = {0, 0, 0};
    const float* gtb  = 0;
    const int*   lbl  = 0;
    for (int i = 0; i < n_in; i++) {
        switch (in_sizes[i]) {
            case NB * HW0 * NC: c[0] = (const float*)d_in[i]; break;
            case NB * HW1 * NC: c[1] = (const float*)d_in[i]; break;
            case NB * HW2 * NC: c[2] = (const float*)d_in[i]; break;
            case NB * HW0 * 4:  r[0] = (const float*)d_in[i]; break;
            case NB * HW1 * 4:  r[1] = (const float*)d_in[i]; break;
            case NB * HW2 * 4:  r[2] = (const float*)d_in[i]; break;
            case NB * NGT * 4:  gtb  = (const float*)d_in[i]; break;
            case NB * NGT:      lbl  = (const int*)d_in[i];   break;
        }
    }

    k_chunkmin<<<NB * CHT, 128>>>(r[0], r[1], r[2], gtb);
    k_loss<<<NTASK * 32 / 128, 128>>>(c[0], c[1], c[2], r[0], r[1], r[2], gtb, lbl);
    k_fin<<<1, 32>>>((float*)d_out);
}

// round 3
// speedup vs baseline: 1.6554x; 1.5251x over previous
#include <cuda_runtime.h>
#include <math_constants.h>

// ---------------------------------------------------------------------------
// DetectionLoss — single persistent kernel, one wave (1184 blocks = 8 x 148),
// software grid barrier (monotonic ticket, replay-safe), last-block finalize.
//  phase1: per (b,lvl,chunk-of-100) min d2 over anchors for all 128 gts
//          (packed f32x2 math), stored transposed [task][chunk].
//  phase2: per task-warp: min over chunk mins, first-chunk, exact first-index
//          recovery (bit-identical arithmetic), CE + L1, smem partials,
//          3 global atomics per block.
//  finalize: last ticket on bar1 reads+resets g_acc, writes out[3].
// ---------------------------------------------------------------------------

#define NLVL 3
#define NB   16
#define NGT  128
#define NC   80
#define HW0  25600
#define HW1  6400
#define HW2  1600
#define CHUNK 100
#define CL0  256                  // HW0/CHUNK
#define CL1  64
#define CL2  16
#define CPB  (CL0 + CL1 + CL2)    // 336 items per batch
#define NITEMS (NB * CPB)         // 5376
#define MAXCH 256
#define NTASK (NLVL * NB * NGT)   // 6144
#define NBLK 1184                 // 8 * 148 — exactly one wave
#define NWARP (NBLK * 4)          // 4736

__device__ float g_chunkmin[NTASK * MAXCH];   // [task][chunk], 6.3MB
__device__ float g_acc[3];                    // zero-init; exch-reset each replay
__device__ unsigned g_bar0;                   // monotonic tickets (never reset)
__device__ unsigned g_bar1;

// ---- packed f32x2 helpers (sm_10x) ----
__device__ __forceinline__ unsigned long long pack2(float lo, float hi) {
    unsigned long long r;
    asm("mov.b64 %0, {%1, %2};" : "=l"(r) : "f"(lo), "f"(hi));
    return r;
}
__device__ __forceinline__ void unpack2(unsigned long long v, float& lo, float& hi) {
    asm("mov.b64 {%0, %1}, %2;" : "=f"(lo), "=f"(hi) : "l"(v));
}
__device__ __forceinline__ unsigned long long add2(unsigned long long a, unsigned long long b) {
    unsigned long long r;
    asm("add.rn.f32x2 %0, %1, %2;" : "=l"(r) : "l"(a), "l"(b));
    return r;
}
__device__ __forceinline__ unsigned long long mul2(unsigned long long a, unsigned long long b) {
    unsigned long long r;
    asm("mul.rn.f32x2 %0, %1, %2;" : "=l"(r) : "l"(a), "l"(b));
    return r;
}
__device__ __forceinline__ unsigned long long fma2(unsigned long long a, unsigned long long b,
                                                   unsigned long long c) {
    unsigned long long r;
    asm("fma.rn.f32x2 %0, %1, %2, %3;" : "=l"(r) : "l"(a), "l"(b), "l"(c));
    return r;
}

__global__ void __launch_bounds__(128, 10) k_all(
    const float* __restrict__ r0, const float* __restrict__ r1,
    const float* __restrict__ r2, const float* __restrict__ c0,
    const float* __restrict__ c1, const float* __restrict__ c2,
    const float* __restrict__ gtb, const int* __restrict__ lbl,
    float* __restrict__ out) {
    __shared__ __align__(16) float s_ax[CHUNK];
    __shared__ __align__(16) float s_ay[CHUNK];
    __shared__ float s_part[3];

    const int tid = threadIdx.x;

    // ---------------- phase 1: chunk mins ----------------
    for (int item = blockIdx.x; item < NITEMS; item += NBLK) {
        const int b = item / CPB;
        const int r = item % CPB;
        int lvl, chunk, HW;
        const float* reg;
        if (r < CL0)            { lvl = 0; chunk = r;             reg = r0; HW = HW0; }
        else if (r < CL0 + CL1) { lvl = 1; chunk = r - CL0;       reg = r1; HW = HW1; }
        else                    { lvl = 2; chunk = r - CL0 - CL1; reg = r2; HW = HW2; }
        const int cs = chunk * CHUNK;

        __syncthreads();   // protect smem reuse across items
        if (tid < CHUNK) {
            const float4 v = ((const float4*)(reg + ((size_t)b * HW + cs) * 4))[tid];
            s_ax[tid] = v.x;
            s_ay[tid] = v.y;
        }
        __syncthreads();

        const int gt = tid;  // 0..127
        const float2 g = *(const float2*)(gtb + ((size_t)(b * NGT + gt)) * 4);
        const unsigned long long ngx = pack2(-g.x, -g.x);
        const unsigned long long ngy = pack2(-g.y, -g.y);

        float a0 = CUDART_INF_F, a1 = CUDART_INF_F, a2 = CUDART_INF_F, a3 = CUDART_INF_F;
#pragma unroll 5
        for (int i = 0; i < CHUNK; i += 4) {
            const float4 ax = *(const float4*)(s_ax + i);
            const float4 ay = *(const float4*)(s_ay + i);
            const unsigned long long dx0 = add2(pack2(ax.x, ax.y), ngx);
            const unsigned long long dx1 = add2(pack2(ax.z, ax.w), ngx);
            const unsigned long long dy0 = add2(pack2(ay.x, ay.y), ngy);
            const unsigned long long dy1 = add2(pack2(ay.z, ay.w), ngy);
            const unsigned long long p0 = fma2(dy0, dy0, mul2(dx0, dx0));
            const unsigned long long p1 = fma2(dy1, dy1, mul2(dx1, dx1));
            float d0, d1, d2, d3;
            unpack2(p0, d0, d1);
            unpack2(p1, d2, d3);
            a0 = fminf(a0, d0);
            a1 = fminf(a1, d1);
            a2 = fminf(a2, d2);
            a3 = fminf(a3, d3);
        }
        const float m = fminf(fminf(a0, a1), fminf(a2, a3));
        const int task = (lvl * NB + b) * NGT + gt;
        g_chunkmin[(size_t)task * MAXCH + chunk] = m;
    }

    // ---------------- grid barrier (monotonic tickets) ----------------
    if (tid == 0) {
        __threadfence();
        const unsigned t = atomicAdd(&g_bar0, 1u);
        const unsigned target = (t / NBLK + 1u) * NBLK;
        while (atomicAdd(&g_bar0, 0u) < target) __nanosleep(128);
        __threadfence();
    }
    __syncthreads();
    if (tid < 3) s_part[tid] = 0.0f;
    __syncthreads();

    // ---------------- phase 2: loss per task ----------------
    const int lane = tid & 31;
    const int gw   = blockIdx.x * 4 + (tid >> 5);
    for (int w = gw; w < NTASK; w += NWARP) {
        const int lvl = w >> 11;
        const int rr  = w & 2047;
        const int b   = rr >> 7;
        const int n   = rr & 127;
        const int nch = (lvl == 0) ? CL0 : ((lvl == 1) ? CL1 : CL2);

        const size_t tb = (size_t)w * MAXCH;
        float cm[8];
#pragma unroll
        for (int k = 0; k < 8; k++)
            cm[k] = (lane + 32 * k < nch) ? __ldcg(&g_chunkmin[tb + lane + 32 * k])
                                          : CUDART_INF_F;
        float m = cm[0];
#pragma unroll
        for (int k = 1; k < 8; k++) m = fminf(m, cm[k]);
#pragma unroll
        for (int o = 16; o; o >>= 1) m = fminf(m, __shfl_xor_sync(0xFFFFFFFFu, m, o));

        const float wt = (__fsqrt_rn(m) < 2.5f) ? 1.0f : 0.0f;

        int cand = 0x7FFFFFFF;
#pragma unroll
        for (int k = 0; k < 8; k++)
            if (cm[k] == m) cand = min(cand, lane + 32 * k);
#pragma unroll
        for (int o = 16; o; o >>= 1) cand = min(cand, __shfl_xor_sync(0xFFFFFFFFu, cand, o));
        const int cs = cand * CHUNK;

        const float* cls = (lvl == 0) ? c0 : ((lvl == 1) ? c1 : c2);
        const float* reg = (lvl == 0) ? r0 : ((lvl == 1) ? r1 : r2);
        const int    HW  = (lvl == 0) ? HW0 : ((lvl == 1) ? HW1 : HW2);

        // exact first-index recovery (bit-identical arithmetic to phase 1)
        const float2 g = *(const float2*)(gtb + ((size_t)(b * NGT + n)) * 4);
        int midx = 0x7FFFFFFF;
#pragma unroll
        for (int j = 0; j < 4; j++) {
            const int a = lane + 32 * j;
            if (a < CHUNK) {
                const float2 p = *(const float2*)(reg + ((size_t)b * HW + cs + a) * 4);
                const float dx = __fadd_rn(p.x, -g.x);
                const float dy = __fadd_rn(p.y, -g.y);
                const float d2 = __fmaf_rn(dy, dy, __fmul_rn(dx, dx));
                if (d2 == m) midx = min(midx, cs + a);
            }
        }
#pragma unroll
        for (int o = 16; o; o >>= 1) midx = min(midx, __shfl_xor_sync(0xFFFFFFFFu, midx, o));
        const int idx = midx;

        // CE via warp logsumexp over 80 logits
        const float* row = cls + ((size_t)b * HW + idx) * NC;
        const float x0 = row[lane];
        const float x1 = row[lane + 32];
        const float x2 = (lane < 16) ? row[lane + 64] : -CUDART_INF_F;

        float mx = fmaxf(fmaxf(x0, x1), x2);
#pragma unroll
        for (int o = 16; o; o >>= 1) mx = fmaxf(mx, __shfl_xor_sync(0xFFFFFFFFu, mx, o));

        float s = expf(x0 - mx) + expf(x1 - mx) + ((lane < 16) ? expf(x2 - mx) : 0.0f);

        const int label = lbl[b * NGT + n];
        float xl = 0.0f;
        if (lane == label)           xl = x0;
        else if (lane + 32 == label) xl = x1;
        else if (lane + 64 == label) xl = x2;

#pragma unroll
        for (int o = 16; o; o >>= 1) {
            s  += __shfl_xor_sync(0xFFFFFFFFu, s, o);
            xl += __shfl_xor_sync(0xFFFFFFFFu, xl, o);
        }

        if (lane == 0) {
            const float ce = (mx + logf(s)) - xl;
            const float4 p  = *(const float4*)(reg + ((size_t)b * HW + idx) * 4);
            const float4 gg = *(const float4*)(gtb + ((size_t)(b * NGT + n)) * 4);
            const float l1 = fabsf(p.x - gg.x) + fabsf(p.y - gg.y) +
                             fabsf(p.z - gg.z) + fabsf(p.w - gg.w);
            atomicAdd(&s_part[0], ce * wt);
            atomicAdd(&s_part[1], l1 * wt);
            atomicAdd(&s_part[2], wt);
        }
    }

    // ---------------- block partial -> global, last block finalizes ----------
    __syncthreads();
    if (tid == 0) {
        atomicAdd(&g_acc[0], s_part[0]);
        atomicAdd(&g_acc[1], s_part[1]);
        atomicAdd(&g_acc[2], s_part[2]);
        __threadfence();
        const unsigned t2 = atomicAdd(&g_bar1, 1u);
        if (t2 % NBLK == NBLK - 1u) {   // last arriver: all adds visible
            const float a0 = atomicExch(&g_acc[0], 0.0f);
            const float a1 = atomicExch(&g_acc[1], 0.0f);
            const float np = atomicExch(&g_acc[2], 0.0f);
            const float denom = fmaxf(np, 1.0f);
            out[0] = a0 / denom;
            out[1] = a1 / denom;
            out[2] = np;
        }
    }
}

// ---------------------------------------------------------------------------
extern "C" void kernel_launch(void* const* d_in, const int* in_sizes, int n_in,
                              void* d_out, int out_size) {
    const float* c[3] = {0, 0, 0};
    const float* r[3] = {0, 0, 0};
    const float* gtb  = 0;
    const int*   lbl  = 0;
    for (int i = 0; i < n_in; i++) {
        switch (in_sizes[i]) {
            case NB * HW0 * NC: c[0] = (const float*)d_in[i]; break;
            case NB * HW1 * NC: c[1] = (const float*)d_in[i]; break;
            case NB * HW2 * NC: c[2] = (const float*)d_in[i]; break;
            case NB * HW0 * 4:  r[0] = (const float*)d_in[i]; break;
            case NB * HW1 * 4:  r[1] = (const float*)d_in[i]; break;
            case NB * HW2 * 4:  r[2] = (const float*)d_in[i]; break;
            case NB * NGT * 4:  gtb  = (const float*)d_in[i]; break;
            case NB * NGT:      lbl  = (const int*)d_in[i];   break;
        }
    }

    k_all<<<NBLK, 128>>>(r[0], r[1], r[2], c[0], c[1], c[2], gtb, lbl,
                         (float*)d_out);
}